// round 2
// baseline (speedup 1.0000x reference)
#include <cuda_runtime.h>
#include <math.h>

#define BB 2
#define TT 2048
#define DD 1024
#define LL 4
#define VV 32000
#define FF (4*DD)
#define NROWS (BB*TT)   // 4096

// ---------------- scratch (device globals; no allocations allowed) ----------
__device__ float g_X[(size_t)NROWS*DD];        // residual stream      16.8 MB
__device__ float g_H[(size_t)NROWS*DD];        // ln output / y        16.8 MB
__device__ float g_Q[(size_t)NROWS*DD];
__device__ float g_K[(size_t)NROWS*DD];
__device__ float g_V[(size_t)NROWS*DD];
__device__ float g_S[(size_t)BB*TT*TT];        // attention scores     33.6 MB
__device__ float g_F[(size_t)NROWS*FF];        // ffn hidden           67.1 MB

// ---------------- embed: x = emb[tok] + pos ---------------------------------
__global__ void embed_k(const int* __restrict__ tok,
                        const float* __restrict__ emb,
                        const float* __restrict__ pos,
                        float* __restrict__ X)
{
    int idx = blockIdx.x * blockDim.x + threadIdx.x;      // over NROWS*DD/4
    int total = NROWS * (DD/4);
    if (idx >= total) return;
    int d4 = idx % (DD/4);
    int bt = idx / (DD/4);
    int t  = bt % TT;
    int token = tok[bt];
    float4 e = reinterpret_cast<const float4*>(emb + (size_t)token*DD)[d4];
    float4 p = reinterpret_cast<const float4*>(pos + (size_t)t*DD)[d4];
    float4 o; o.x=e.x+p.x; o.y=e.y+p.y; o.z=e.z+p.z; o.w=e.w+p.w;
    reinterpret_cast<float4*>(X + (size_t)bt*DD)[d4] = o;
}

// ---------------- layernorm (one block per row, D=1024, 256 thr) ------------
__global__ void ln_k(const float* __restrict__ X, float* __restrict__ Y,
                     const float* __restrict__ g, const float* __restrict__ b)
{
    int row = blockIdx.x;
    int tid = threadIdx.x;                                // 256, 1 float4 each
    const float4* x4 = reinterpret_cast<const float4*>(X + (size_t)row*DD);
    float4 v = x4[tid];
    __shared__ float sh[256];

    float s = v.x + v.y + v.z + v.w;
    sh[tid] = s; __syncthreads();
    for (int o = 128; o > 0; o >>= 1) { if (tid < o) sh[tid] += sh[tid+o]; __syncthreads(); }
    float mu = sh[0] * (1.0f/DD);
    __syncthreads();

    float c0=v.x-mu, c1=v.y-mu, c2=v.z-mu, c3=v.w-mu;
    sh[tid] = c0*c0 + c1*c1 + c2*c2 + c3*c3; __syncthreads();
    for (int o = 128; o > 0; o >>= 1) { if (tid < o) sh[tid] += sh[tid+o]; __syncthreads(); }
    float inv = rsqrtf(sh[0] * (1.0f/DD) + 1e-5f);

    float4 gv = reinterpret_cast<const float4*>(g)[tid];
    float4 bv = reinterpret_cast<const float4*>(b)[tid];
    float4 o4;
    o4.x = c0*inv*gv.x + bv.x;
    o4.y = c1*inv*gv.y + bv.y;
    o4.z = c2*inv*gv.z + bv.z;
    o4.w = c3*inv*gv.w + bv.w;
    reinterpret_cast<float4*>(Y + (size_t)row*DD)[tid] = o4;
}

// ---------------- causal softmax over row t (writes 0 beyond t) -------------
__global__ void softmax_k(float* __restrict__ S)
{
    int t = blockIdx.x, b = blockIdx.y;
    int tid = threadIdx.x;                                // 256
    float* row = S + ((size_t)b*TT + t) * TT;
    __shared__ float sh[256];

    float mx = -1e30f;
    for (int c = tid; c <= t; c += 256) mx = fmaxf(mx, row[c]);
    sh[tid] = mx; __syncthreads();
    for (int o = 128; o > 0; o >>= 1) { if (tid < o) sh[tid] = fmaxf(sh[tid], sh[tid+o]); __syncthreads(); }
    mx = sh[0]; __syncthreads();

    float sum = 0.f;
    for (int c = tid; c <= t; c += 256) sum += __expf(row[c] - mx);
    sh[tid] = sum; __syncthreads();
    for (int o = 128; o > 0; o >>= 1) { if (tid < o) sh[tid] += sh[tid+o]; __syncthreads(); }
    float inv = 1.0f / sh[0];

    for (int c = tid; c < TT; c += 256)
        row[c] = (c <= t) ? __expf(row[c] - mx) * inv : 0.0f;
}

// ---------------- SGEMM: C = alpha*A@op(B) (+bias) (+relu) (+addm) ----------
// A: M x K row-major. B: NN -> K x N row-major, TB -> N x K row-major (C=A*B^T).
// Tiles 128x128x8, 256 threads, 8x8 per thread (4+4 split to reduce LDS conflicts).
// All of M,N multiples of 128; K multiple of 8. Batched via blockIdx.z strides.
template<bool TB, bool RELU>
__global__ __launch_bounds__(256) void sgemm_k(
    const float* __restrict__ A, const float* __restrict__ B,
    float* __restrict__ C,
    int M, int N, int K, float alpha,
    const float* __restrict__ bias,
    const float* __restrict__ addm,
    long sA, long sB, long sC, long sAdd)
{
    __shared__ float As[8][128];
    __shared__ float Bs[8][128];

    A += (long)blockIdx.z * sA;
    B += (long)blockIdx.z * sB;
    C += (long)blockIdx.z * sC;
    if (addm) addm += (long)blockIdx.z * sAdd;

    const int tid = threadIdx.x;
    const int tx = tid & 15;
    const int ty = tid >> 4;
    const int rowBlk = blockIdx.y * 128;
    const int colBlk = blockIdx.x * 128;

    const int lr  = tid >> 1;          // 0..127 (A / TB-B loads)
    const int lc4 = (tid & 1) * 4;     // 0 or 4
    const int brw = tid >> 5;          // 0..7   (NN-B loads)
    const int bc4 = (tid & 31) * 4;

    float acc[8][8];
#pragma unroll
    for (int i = 0; i < 8; i++)
#pragma unroll
        for (int j = 0; j < 8; j++) acc[i][j] = 0.f;

    for (int k0 = 0; k0 < K; k0 += 8) {
        float4 av = *reinterpret_cast<const float4*>(A + (long)(rowBlk + lr)*K + k0 + lc4);
        As[lc4+0][lr] = av.x; As[lc4+1][lr] = av.y;
        As[lc4+2][lr] = av.z; As[lc4+3][lr] = av.w;
        if (TB) {
            float4 bv = *reinterpret_cast<const float4*>(B + (long)(colBlk + lr)*K + k0 + lc4);
            Bs[lc4+0][lr] = bv.x; Bs[lc4+1][lr] = bv.y;
            Bs[lc4+2][lr] = bv.z; Bs[lc4+3][lr] = bv.w;
        } else {
            float4 bv = *reinterpret_cast<const float4*>(B + (long)(k0 + brw)*N + colBlk + bc4);
            *reinterpret_cast<float4*>(&Bs[brw][bc4]) = bv;
        }
        __syncthreads();
#pragma unroll
        for (int kk = 0; kk < 8; kk++) {
            float4 a0 = *reinterpret_cast<const float4*>(&As[kk][ty*4]);
            float4 a1 = *reinterpret_cast<const float4*>(&As[kk][64 + ty*4]);
            float4 b0 = *reinterpret_cast<const float4*>(&Bs[kk][tx*4]);
            float4 b1 = *reinterpret_cast<const float4*>(&Bs[kk][64 + tx*4]);
            float ar[8] = {a0.x,a0.y,a0.z,a0.w,a1.x,a1.y,a1.z,a1.w};
            float br[8] = {b0.x,b0.y,b0.z,b0.w,b1.x,b1.y,b1.z,b1.w};
#pragma unroll
            for (int i = 0; i < 8; i++)
#pragma unroll
                for (int j = 0; j < 8; j++)
                    acc[i][j] += ar[i] * br[j];
        }
        __syncthreads();
    }

    float4 bias0 = make_float4(0.f,0.f,0.f,0.f), bias1 = bias0;
    if (bias) {
        bias0 = *reinterpret_cast<const float4*>(bias + colBlk + tx*4);
        bias1 = *reinterpret_cast<const float4*>(bias + colBlk + 64 + tx*4);
    }

#pragma unroll
    for (int i = 0; i < 8; i++) {
        int r = rowBlk + ((i < 4) ? (ty*4 + i) : (64 + ty*4 + (i-4)));
#pragma unroll
        for (int jh = 0; jh < 2; jh++) {
            int c = colBlk + jh*64 + tx*4;
            int j0 = jh*4;
            float4 bb = jh ? bias1 : bias0;
            float4 v;
            v.x = acc[i][j0+0]*alpha + bb.x;
            v.y = acc[i][j0+1]*alpha + bb.y;
            v.z = acc[i][j0+2]*alpha + bb.z;
            v.w = acc[i][j0+3]*alpha + bb.w;
            if (RELU) {
                v.x = fmaxf(v.x, 0.f); v.y = fmaxf(v.y, 0.f);
                v.z = fmaxf(v.z, 0.f); v.w = fmaxf(v.w, 0.f);
            }
            if (addm) {
                float4 ad = *reinterpret_cast<const float4*>(addm + (long)r*N + c);
                v.x += ad.x; v.y += ad.y; v.z += ad.z; v.w += ad.w;
            }
            *reinterpret_cast<float4*>(C + (long)r*N + c) = v;
        }
    }
}

// ---------------- host-side GEMM dispatch ------------------------------------
static void gemm(const float* A, const float* B, float* C,
                 int M, int N, int K, float alpha,
                 const float* bias, const float* addm,
                 bool tb, bool relu, int batch,
                 long sA, long sB, long sC, long sAdd)
{
    dim3 grid(N/128, M/128, batch), blk(256);
    if (tb)
        sgemm_k<true,false><<<grid, blk>>>(A,B,C,M,N,K,alpha,bias,addm,sA,sB,sC,sAdd);
    else if (relu)
        sgemm_k<false,true><<<grid, blk>>>(A,B,C,M,N,K,alpha,bias,addm,sA,sB,sC,sAdd);
    else
        sgemm_k<false,false><<<grid, blk>>>(A,B,C,M,N,K,alpha,bias,addm,sA,sB,sC,sAdd);
}

// ---------------- entry ------------------------------------------------------
extern "C" void kernel_launch(void* const* d_in, const int* in_sizes, int n_in,
                              void* d_out, int out_size)
{
    const int*   tokens = (const int*)  d_in[0];
    const float* emb    = (const float*)d_in[1];
    const float* pos    = (const float*)d_in[2];
    const float* Wq     = (const float*)d_in[3];
    const float* Wk     = (const float*)d_in[4];
    const float* Wv     = (const float*)d_in[5];
    const float* w1     = (const float*)d_in[6];
    const float* b1     = (const float*)d_in[7];
    const float* w2     = (const float*)d_in[8];
    const float* b2     = (const float*)d_in[9];
    const float* g1     = (const float*)d_in[10];
    const float* bln1   = (const float*)d_in[11];
    const float* g2     = (const float*)d_in[12];
    const float* bln2   = (const float*)d_in[13];
    const float* projw  = (const float*)d_in[14];
    const float* projb  = (const float*)d_in[15];
    float* out = (float*)d_out;

    float *X,*H,*Q,*Kp,*Vp,*S,*Fh;
    cudaGetSymbolAddress((void**)&X,  g_X);
    cudaGetSymbolAddress((void**)&H,  g_H);
    cudaGetSymbolAddress((void**)&Q,  g_Q);
    cudaGetSymbolAddress((void**)&Kp, g_K);
    cudaGetSymbolAddress((void**)&Vp, g_V);
    cudaGetSymbolAddress((void**)&S,  g_S);
    cudaGetSymbolAddress((void**)&Fh, g_F);

    const float scale = 0.03125f;   // 1/sqrt(1024)

    // x = emb[tokens] + pos
    {
        int total = NROWS * (DD/4);
        embed_k<<<(total + 255)/256, 256>>>(tokens, emb, pos, X);
    }

    for (int l = 0; l < LL; l++) {
        const float* Wq_l  = Wq  + (size_t)l*DD*DD;
        const float* Wk_l  = Wk  + (size_t)l*DD*DD;
        const float* Wv_l  = Wv  + (size_t)l*DD*DD;
        const float* w1_l  = w1  + (size_t)l*DD*FF;
        const float* b1_l  = b1  + (size_t)l*FF;
        const float* w2_l  = w2  + (size_t)l*FF*DD;
        const float* b2_l  = b2  + (size_t)l*DD;

        // h = ln1(x)
        ln_k<<<NROWS, 256>>>(X, H, g1 + (size_t)l*DD, bln1 + (size_t)l*DD);

        // q,k,v = h @ W
        gemm(H, Wq_l, Q,  NROWS, DD, DD, 1.f, nullptr, nullptr, false, false, 1, 0,0,0,0);
        gemm(H, Wk_l, Kp, NROWS, DD, DD, 1.f, nullptr, nullptr, false, false, 1, 0,0,0,0);
        gemm(H, Wv_l, Vp, NROWS, DD, DD, 1.f, nullptr, nullptr, false, false, 1, 0,0,0,0);

        // s = (q @ k^T) * scale   (batched over B)
        gemm(Q, Kp, S, TT, TT, DD, scale, nullptr, nullptr, true, false, BB,
             (long)TT*DD, (long)TT*DD, (long)TT*TT, 0);

        // causal softmax in-place
        {
            dim3 grid(TT, BB);
            softmax_k<<<grid, 256>>>(S);
        }

        // x = s @ v + x   (batched, residual add)
        gemm(S, Vp, X, TT, DD, TT, 1.f, nullptr, X, false, false, BB,
             (long)TT*TT, (long)TT*DD, (long)TT*DD, (long)TT*DD);

        // y = ln2(x) -> H
        ln_k<<<NROWS, 256>>>(X, H, g2 + (size_t)l*DD, bln2 + (size_t)l*DD);

        // ff_mid = relu(y @ w1 + b1)
        gemm(H, w1_l, Fh, NROWS, FF, DD, 1.f, b1_l, nullptr, false, true, 1, 0,0,0,0);

        // x = ff_mid @ w2 + b2 + y
        gemm(Fh, w2_l, X, NROWS, DD, FF, 1.f, b2_l, H, false, false, 1, 0,0,0,0);
    }

    // logits = x @ proj_w + proj_b  -> d_out
    gemm(X, projw, out, NROWS, VV, DD, 1.f, projb, nullptr, false, false, 1, 0,0,0,0);
}

// round 5
// speedup vs baseline: 2.1491x; 2.1491x over previous
#include <cuda_runtime.h>
#include <cuda_bf16.h>
#include <math.h>
#include <stdint.h>

#define BB 2
#define TT 2048
#define DD 1024
#define LL 4
#define VV 32000
#define FF (4*DD)
#define NROWS (BB*TT)   // 4096

// WT scratch layout (elements): per layer: WqT,WkT,WvT (DD*DD each), w1T (DD*FF), w2T (FF*DD)
#define LYR_BLK (3*DD*DD + DD*FF + FF*DD)
#define PROJ_OFF ((size_t)LL*LYR_BLK)
#define WT_TOTAL (PROJ_OFF + (size_t)DD*VV)

// ---------------- scratch (device globals; no allocations allowed) ----------
__device__ float g_X[(size_t)NROWS*DD];
__device__ float g_H[(size_t)NROWS*DD];
__device__ float g_QKV[(size_t)3*NROWS*DD];
__device__ float g_S[(size_t)BB*TT*TT];
__device__ float g_F[(size_t)NROWS*FF];
__device__ __nv_bfloat16 g_WTh[WT_TOTAL];
__device__ __nv_bfloat16 g_WTl[WT_TOTAL];
__device__ __nv_bfloat16 g_VTh[(size_t)BB*DD*TT];
__device__ __nv_bfloat16 g_VTl[(size_t)BB*DD*TT];

// ============================ helpers ========================================
__device__ __forceinline__ uint32_t smem_u32(const void* p) {
    uint32_t a;
    asm("{ .reg .u64 t; cvta.to.shared.u64 t, %1; cvt.u32.u64 %0, t; }" : "=r"(a) : "l"(p));
    return a;
}
// 64B-row swizzle (Swizzle<2,3,3>): XOR byte bits [4:6) with bits [7:9)
#define SWZ64(o) ((o) ^ (((o) >> 3) & 0x30))

__device__ __forceinline__ void ldm_x4(uint32_t* r, uint32_t addr) {
    asm volatile("ldmatrix.sync.aligned.m8n8.x4.shared.b16 {%0,%1,%2,%3}, [%4];"
                 : "=r"(r[0]), "=r"(r[1]), "=r"(r[2]), "=r"(r[3]) : "r"(addr));
}
__device__ __forceinline__ void mma_bf16(float* d, const uint32_t* a, uint32_t b0, uint32_t b1) {
    asm volatile(
        "mma.sync.aligned.m16n8k16.row.col.f32.bf16.bf16.f32 "
        "{%0,%1,%2,%3}, {%4,%5,%6,%7}, {%8,%9}, {%0,%1,%2,%3};"
        : "+f"(d[0]), "+f"(d[1]), "+f"(d[2]), "+f"(d[3])
        : "r"(a[0]), "r"(a[1]), "r"(a[2]), "r"(a[3]), "r"(b0), "r"(b1));
}

__device__ __forceinline__ uint32_t pk2(__nv_bfloat16 a, __nv_bfloat16 b) {
    __nv_bfloat162 t = __halves2bfloat162(a, b);
    return *reinterpret_cast<uint32_t*>(&t);
}
__device__ __forceinline__ void split4(float4 v, uint2& hv, uint2& lv) {
    __nv_bfloat16 h0 = __float2bfloat16(v.x), h1 = __float2bfloat16(v.y);
    __nv_bfloat16 h2 = __float2bfloat16(v.z), h3 = __float2bfloat16(v.w);
    float l0 = v.x - __bfloat162float(h0), l1 = v.y - __bfloat162float(h1);
    float l2 = v.z - __bfloat162float(h2), l3 = v.w - __bfloat162float(h3);
    hv.x = pk2(h0, h1); hv.y = pk2(h2, h3);
    lv.x = pk2(__float2bfloat16(l0), __float2bfloat16(l1));
    lv.y = pk2(__float2bfloat16(l2), __float2bfloat16(l3));
}

// SMEM stage layout (per stage, 32 KB): Ah[128][32]bf16 @0 (8KB), Al @8192,
// Bh[128][32] @16384, Bl @24576. Two stages = 64 KB dynamic.
#define STG_SZ 32768
#define SHM_TOTAL (2*STG_SZ)
#define BK 32

// ---------------- mma.sync GEMM: C = alpha*A@B^T (+bias)(+relu)(+addm) ------
// A: [M][K] f32 row-major (bf16 hi/lo split in-register).
// B: BMODE0 pre-split bf16 [N][K] hi/lo; BMODE1 f32 [N][K] split in-register.
// Tile 128x128x32, 256 thr, warps 2(m)x4(n), warp tile 64x32, 3-term split MMA.
template<int BMODE>
__global__ __launch_bounds__(256) void mma_gemm_k(
    const float* __restrict__ A,
    const __nv_bfloat16* __restrict__ Bhp, const __nv_bfloat16* __restrict__ Blp,
    const float* __restrict__ Bf,
    float* __restrict__ C,
    int M, int N, int K, float alpha,
    const float* __restrict__ bias,
    const float* __restrict__ addm,
    int relu,
    long sA, long sB, long sC, long sAdd)
{
    extern __shared__ char smem[];
    const uint32_t smb = smem_u32(smem);
    const int tid = threadIdx.x;

    A += (long)blockIdx.z * sA;
    if (BMODE == 0) { Bhp += (long)blockIdx.z * sB; Blp += (long)blockIdx.z * sB; }
    else            { Bf  += (long)blockIdx.z * sB; }
    C += (long)blockIdx.z * sC;
    if (addm) addm += (long)blockIdx.z * sAdd;

    const int rowBlk = blockIdx.y * 128;
    const int colBlk = blockIdx.x * 128;

    const int lr   = tid >> 1;     // 0..127: tile row handled by this thread
    const int half = tid & 1;      // which 16-element half of the 32-wide chunk

    const float* aptr = A + (long)(rowBlk + lr) * K + half * 16;
    const float* bfptr = nullptr;
    const __nv_bfloat16 *bhptr = nullptr, *blptr = nullptr;
    if (BMODE == 1) bfptr = Bf + (long)(colBlk + lr) * K + half * 16;
    else { bhptr = Bhp + (long)(colBlk + lr) * K + half * 16;
           blptr = Blp + (long)(colBlk + lr) * K + half * 16; }

    float acc[4][4][4];
#pragma unroll
    for (int i = 0; i < 4; i++)
#pragma unroll
        for (int j = 0; j < 4; j++)
#pragma unroll
            for (int k = 0; k < 4; k++) acc[i][j][k] = 0.f;

    const int w = tid >> 5, lane = tid & 31;
    const int wm = (w & 1) * 64;        // warp row offset in tile
    const int wn = (w >> 1) * 32;       // warp col offset in tile

    const int nCh = K / BK;

    // ---- prologue: chunk 0 -> stage 0 ----
    {
        float4 ar[4];
#pragma unroll
        for (int i = 0; i < 4; i++)
            ar[i] = *reinterpret_cast<const float4*>(aptr + i * 4);
        char* st0 = smem;
#pragma unroll
        for (int i = 0; i < 4; i++) {
            uint2 hv, lv; split4(ar[i], hv, lv);
            uint32_t off = SWZ64((uint32_t)(lr * 64 + half * 32 + i * 8));
            *reinterpret_cast<uint2*>(st0 + off) = hv;
            *reinterpret_cast<uint2*>(st0 + 8192 + off) = lv;
        }
        if (BMODE == 0) {
#pragma unroll
            for (int i = 0; i < 2; i++) {
                uint4 vh = *reinterpret_cast<const uint4*>(bhptr + i * 8);
                uint4 vl = *reinterpret_cast<const uint4*>(blptr + i * 8);
                uint32_t off = SWZ64((uint32_t)(lr * 64 + half * 32 + i * 16));
                *reinterpret_cast<uint4*>(st0 + 16384 + off) = vh;
                *reinterpret_cast<uint4*>(st0 + 24576 + off) = vl;
            }
        } else {
            float4 br[4];
#pragma unroll
            for (int i = 0; i < 4; i++)
                br[i] = *reinterpret_cast<const float4*>(bfptr + i * 4);
#pragma unroll
            for (int i = 0; i < 4; i++) {
                uint2 hv, lv; split4(br[i], hv, lv);
                uint32_t off = SWZ64((uint32_t)(lr * 64 + half * 32 + i * 8));
                *reinterpret_cast<uint2*>(st0 + 16384 + off) = hv;
                *reinterpret_cast<uint2*>(st0 + 24576 + off) = lv;
            }
        }
    }
    __syncthreads();

    for (int c = 0; c < nCh; c++) {
        // ---- prefetch chunk c+1 into registers ----
        float4 ar[4], br[4];
        uint4 bh2[2], bl2[2];
        const bool pf = (c + 1 < nCh);
        if (pf) {
            int k1 = (c + 1) * BK;
#pragma unroll
            for (int i = 0; i < 4; i++)
                ar[i] = *reinterpret_cast<const float4*>(aptr + k1 + i * 4);
            if (BMODE == 0) {
#pragma unroll
                for (int i = 0; i < 2; i++) {
                    bh2[i] = *reinterpret_cast<const uint4*>(bhptr + k1 + i * 8);
                    bl2[i] = *reinterpret_cast<const uint4*>(blptr + k1 + i * 8);
                }
            } else {
#pragma unroll
                for (int i = 0; i < 4; i++)
                    br[i] = *reinterpret_cast<const float4*>(bfptr + k1 + i * 4);
            }
        }

        // ---- compute on stage c&1 ----
        {
            const uint32_t sb = smb + (uint32_t)(c & 1) * STG_SZ;
#pragma unroll
            for (int ks = 0; ks < 2; ks++) {
                uint32_t ah[4][4], al[4][4];
#pragma unroll
                for (int mt = 0; mt < 4; mt++) {
                    uint32_t off = SWZ64((uint32_t)((wm + mt * 16 + (lane & 15)) * 64
                                                    + ks * 32 + (lane >> 4) * 16));
                    ldm_x4(ah[mt], sb + off);
                    ldm_x4(al[mt], sb + 8192 + off);
                }
                uint32_t bh[4][2], bl[4][2];
#pragma unroll
                for (int nt2 = 0; nt2 < 2; nt2++) {
                    uint32_t off = SWZ64((uint32_t)((wn + nt2 * 16 + ((lane >> 4) & 1) * 8 + (lane & 7)) * 64
                                                    + ks * 32 + ((lane >> 3) & 1) * 16));
                    uint32_t r[4];
                    ldm_x4(r, sb + 16384 + off);
                    bh[nt2 * 2][0] = r[0]; bh[nt2 * 2][1] = r[1];
                    bh[nt2 * 2 + 1][0] = r[2]; bh[nt2 * 2 + 1][1] = r[3];
                    ldm_x4(r, sb + 24576 + off);
                    bl[nt2 * 2][0] = r[0]; bl[nt2 * 2][1] = r[1];
                    bl[nt2 * 2 + 1][0] = r[2]; bl[nt2 * 2 + 1][1] = r[3];
                }
#pragma unroll
                for (int mt = 0; mt < 4; mt++)
#pragma unroll
                    for (int nt = 0; nt < 4; nt++) {
                        mma_bf16(acc[mt][nt], ah[mt], bh[nt][0], bh[nt][1]);
                        mma_bf16(acc[mt][nt], ah[mt], bl[nt][0], bl[nt][1]);
                        mma_bf16(acc[mt][nt], al[mt], bh[nt][0], bh[nt][1]);
                    }
            }
        }

        // ---- store prefetched regs into stage (c+1)&1 ----
        if (pf) {
            char* stn = smem + ((c + 1) & 1) * STG_SZ;
#pragma unroll
            for (int i = 0; i < 4; i++) {
                uint2 hv, lv; split4(ar[i], hv, lv);
                uint32_t off = SWZ64((uint32_t)(lr * 64 + half * 32 + i * 8));
                *reinterpret_cast<uint2*>(stn + off) = hv;
                *reinterpret_cast<uint2*>(stn + 8192 + off) = lv;
            }
            if (BMODE == 0) {
#pragma unroll
                for (int i = 0; i < 2; i++) {
                    uint32_t off = SWZ64((uint32_t)(lr * 64 + half * 32 + i * 16));
                    *reinterpret_cast<uint4*>(stn + 16384 + off) = bh2[i];
                    *reinterpret_cast<uint4*>(stn + 24576 + off) = bl2[i];
                }
            } else {
#pragma unroll
                for (int i = 0; i < 4; i++) {
                    uint2 hv, lv; split4(br[i], hv, lv);
                    uint32_t off = SWZ64((uint32_t)(lr * 64 + half * 32 + i * 8));
                    *reinterpret_cast<uint2*>(stn + 16384 + off) = hv;
                    *reinterpret_cast<uint2*>(stn + 24576 + off) = lv;
                }
            }
        }
        __syncthreads();
    }

    // ---- epilogue: fragment -> gmem with alpha/bias/relu/addm ----
#pragma unroll
    for (int mt = 0; mt < 4; mt++) {
        int r0 = rowBlk + wm + mt * 16 + (lane >> 2);
#pragma unroll
        for (int nt = 0; nt < 4; nt++) {
            int cc = colBlk + wn + nt * 8 + (lane & 3) * 2;
            float2 v0, v1;
            v0.x = acc[mt][nt][0] * alpha; v0.y = acc[mt][nt][1] * alpha;
            v1.x = acc[mt][nt][2] * alpha; v1.y = acc[mt][nt][3] * alpha;
            if (bias) {
                float2 bb = *reinterpret_cast<const float2*>(bias + cc);
                v0.x += bb.x; v0.y += bb.y; v1.x += bb.x; v1.y += bb.y;
            }
            if (relu) {
                v0.x = fmaxf(v0.x, 0.f); v0.y = fmaxf(v0.y, 0.f);
                v1.x = fmaxf(v1.x, 0.f); v1.y = fmaxf(v1.y, 0.f);
            }
            if (addm) {
                float2 a0 = *reinterpret_cast<const float2*>(addm + (long)r0 * N + cc);
                float2 a1 = *reinterpret_cast<const float2*>(addm + (long)(r0 + 8) * N + cc);
                v0.x += a0.x; v0.y += a0.y; v1.x += a1.x; v1.y += a1.y;
            }
            *reinterpret_cast<float2*>(C + (long)r0 * N + cc) = v0;
            *reinterpret_cast<float2*>(C + (long)(r0 + 8) * N + cc) = v1;
        }
    }
}

// ---------------- transpose + bf16 split: W[R][C] -> T[C][R] hi/lo ----------
__global__ void tsplit_k(const float* __restrict__ W,
                         __nv_bfloat16* __restrict__ Th, __nv_bfloat16* __restrict__ Tl,
                         int R, int C, long sIn, long sOut)
{
    __shared__ float t[32][33];
    W  += (long)blockIdx.z * sIn;
    Th += (long)blockIdx.z * sOut;
    Tl += (long)blockIdx.z * sOut;
    int c0 = blockIdx.x * 32, r0 = blockIdx.y * 32;
    int tx = threadIdx.x, ty = threadIdx.y;
#pragma unroll
    for (int j = 0; j < 32; j += 8)
        t[ty + j][tx] = W[(long)(r0 + ty + j) * C + c0 + tx];
    __syncthreads();
#pragma unroll
    for (int j = 0; j < 32; j += 8) {
        int oc = c0 + ty + j;
        float v = t[tx][ty + j];
        __nv_bfloat16 h = __float2bfloat16(v);
        float lo = v - __bfloat162float(h);
        Th[(long)oc * R + r0 + tx] = h;
        Tl[(long)oc * R + r0 + tx] = __float2bfloat16(lo);
    }
}

// ---------------- embed: x = emb[tok] + pos ---------------------------------
__global__ void embed_k(const int* __restrict__ tok,
                        const float* __restrict__ emb,
                        const float* __restrict__ pos,
                        float* __restrict__ X)
{
    int idx = blockIdx.x * blockDim.x + threadIdx.x;
    int total = NROWS * (DD / 4);
    if (idx >= total) return;
    int d4 = idx % (DD / 4);
    int bt = idx / (DD / 4);
    int t = bt % TT;
    int token = tok[bt];
    float4 e = reinterpret_cast<const float4*>(emb + (size_t)token * DD)[d4];
    float4 p = reinterpret_cast<const float4*>(pos + (size_t)t * DD)[d4];
    float4 o; o.x = e.x + p.x; o.y = e.y + p.y; o.z = e.z + p.z; o.w = e.w + p.w;
    reinterpret_cast<float4*>(X + (size_t)bt * DD)[d4] = o;
}

// ---------------- layernorm --------------------------------------------------
__global__ void ln_k(const float* __restrict__ X, float* __restrict__ Y,
                     const float* __restrict__ g, const float* __restrict__ b)
{
    int row = blockIdx.x;
    int tid = threadIdx.x;
    const float4* x4 = reinterpret_cast<const float4*>(X + (size_t)row * DD);
    float4 v = x4[tid];
    __shared__ float sh[256];

    float s = v.x + v.y + v.z + v.w;
    sh[tid] = s; __syncthreads();
    for (int o = 128; o > 0; o >>= 1) { if (tid < o) sh[tid] += sh[tid + o]; __syncthreads(); }
    float mu = sh[0] * (1.0f / DD);
    __syncthreads();

    float c0 = v.x - mu, c1 = v.y - mu, c2 = v.z - mu, c3 = v.w - mu;
    sh[tid] = c0 * c0 + c1 * c1 + c2 * c2 + c3 * c3; __syncthreads();
    for (int o = 128; o > 0; o >>= 1) { if (tid < o) sh[tid] += sh[tid + o]; __syncthreads(); }
    float inv = rsqrtf(sh[0] * (1.0f / DD) + 1e-5f);

    float4 gv = reinterpret_cast<const float4*>(g)[tid];
    float4 bv = reinterpret_cast<const float4*>(b)[tid];
    float4 o4;
    o4.x = c0 * inv * gv.x + bv.x;
    o4.y = c1 * inv * gv.y + bv.y;
    o4.z = c2 * inv * gv.z + bv.z;
    o4.w = c3 * inv * gv.w + bv.w;
    reinterpret_cast<float4*>(Y + (size_t)row * DD)[tid] = o4;
}

// ---------------- causal softmax ---------------------------------------------
__global__ void softmax_k(float* __restrict__ S)
{
    int t = blockIdx.x, b = blockIdx.y;
    int tid = threadIdx.x;
    float* row = S + ((size_t)b * TT + t) * TT;
    __shared__ float sh[256];

    float mx = -1e30f;
    for (int c = tid; c <= t; c += 256) mx = fmaxf(mx, row[c]);
    sh[tid] = mx; __syncthreads();
    for (int o = 128; o > 0; o >>= 1) { if (tid < o) sh[tid] = fmaxf(sh[tid], sh[tid + o]); __syncthreads(); }
    mx = sh[0]; __syncthreads();

    float sum = 0.f;
    for (int c = tid; c <= t; c += 256) sum += __expf(row[c] - mx);
    sh[tid] = sum; __syncthreads();
    for (int o = 128; o > 0; o >>= 1) { if (tid < o) sh[tid] += sh[tid + o]; __syncthreads(); }
    float inv = 1.0f / sh[0];

    for (int c = tid; c < TT; c += 256)
        row[c] = (c <= t) ? __expf(row[c] - mx) * inv : 0.0f;
}

// ---------------- host-side dispatch -----------------------------------------
static void tcgemm(const float* A, const __nv_bfloat16* Bh, const __nv_bfloat16* Bl,
                   const float* Bf, float* C, int M, int N, int K, float alpha,
                   const float* bias, const float* addm, int relu, int batch,
                   long sA, long sB, long sC, long sAdd)
{
    dim3 grid(N / 128, M / 128, batch), blk(256);
    if (Bf)
        mma_gemm_k<1><<<grid, blk, SHM_TOTAL>>>(A, nullptr, nullptr, Bf, C, M, N, K, alpha, bias, addm, relu, sA, sB, sC, sAdd);
    else
        mma_gemm_k<0><<<grid, blk, SHM_TOTAL>>>(A, Bh, Bl, nullptr, C, M, N, K, alpha, bias, addm, relu, sA, sB, sC, sAdd);
}

static void tsplit(const float* W, __nv_bfloat16* Th, __nv_bfloat16* Tl,
                   int R, int C, int batch, long sIn, long sOut)
{
    dim3 g(C / 32, R / 32, batch), b(32, 8);
    tsplit_k<<<g, b>>>(W, Th, Tl, R, C, sIn, sOut);
}

extern "C" void kernel_launch(void* const* d_in, const int* in_sizes, int n_in,
                              void* d_out, int out_size)
{
    const int*   tokens = (const int*)  d_in[0];
    const float* emb    = (const float*)d_in[1];
    const float* pos    = (const float*)d_in[2];
    const float* Wq     = (const float*)d_in[3];
    const float* Wk     = (const float*)d_in[4];
    const float* Wv     = (const float*)d_in[5];
    const float* w1     = (const float*)d_in[6];
    const float* b1     = (const float*)d_in[7];
    const float* w2     = (const float*)d_in[8];
    const float* b2     = (const float*)d_in[9];
    const float* g1     = (const float*)d_in[10];
    const float* bln1   = (const float*)d_in[11];
    const float* g2     = (const float*)d_in[12];
    const float* bln2   = (const float*)d_in[13];
    const float* projw  = (const float*)d_in[14];
    const float* projb  = (const float*)d_in[15];
    float* out = (float*)d_out;

    cudaFuncSetAttribute(mma_gemm_k<0>, cudaFuncAttributeMaxDynamicSharedMemorySize, SHM_TOTAL);
    cudaFuncSetAttribute(mma_gemm_k<1>, cudaFuncAttributeMaxDynamicSharedMemorySize, SHM_TOTAL);

    float *X, *H, *QKV, *S, *Fh;
    __nv_bfloat16 *WTh, *WTl, *VTh, *VTl;
    cudaGetSymbolAddress((void**)&X,   g_X);
    cudaGetSymbolAddress((void**)&H,   g_H);
    cudaGetSymbolAddress((void**)&QKV, g_QKV);
    cudaGetSymbolAddress((void**)&S,   g_S);
    cudaGetSymbolAddress((void**)&Fh,  g_F);
    cudaGetSymbolAddress((void**)&WTh, g_WTh);
    cudaGetSymbolAddress((void**)&WTl, g_WTl);
    cudaGetSymbolAddress((void**)&VTh, g_VTh);
    cudaGetSymbolAddress((void**)&VTl, g_VTl);

    float* Q  = QKV;
    float* Kp = QKV + (size_t)NROWS * DD;
    float* Vp = QKV + (size_t)2 * NROWS * DD;

    const float scale = 0.03125f;   // 1/sqrt(1024)

    // ---- weight prepass: transpose + bf16 hi/lo split -----------------------
    for (int l = 0; l < LL; l++) {
        size_t base = (size_t)l * LYR_BLK;
        tsplit(Wq + (size_t)l * DD * DD, WTh + base,                   WTl + base,                   DD, DD, 1, 0, 0);
        tsplit(Wk + (size_t)l * DD * DD, WTh + base + (size_t)DD*DD,   WTl + base + (size_t)DD*DD,   DD, DD, 1, 0, 0);
        tsplit(Wv + (size_t)l * DD * DD, WTh + base + (size_t)2*DD*DD, WTl + base + (size_t)2*DD*DD, DD, DD, 1, 0, 0);
        tsplit(w1 + (size_t)l * DD * FF, WTh + base + (size_t)3*DD*DD, WTl + base + (size_t)3*DD*DD, DD, FF, 1, 0, 0);
        tsplit(w2 + (size_t)l * FF * DD, WTh + base + (size_t)3*DD*DD + (size_t)DD*FF,
                                         WTl + base + (size_t)3*DD*DD + (size_t)DD*FF, FF, DD, 1, 0, 0);
    }
    tsplit(projw, WTh + PROJ_OFF, WTl + PROJ_OFF, DD, VV, 1, 0, 0);

    // ---- embed --------------------------------------------------------------
    {
        int total = NROWS * (DD / 4);
        embed_k<<<(total + 255) / 256, 256>>>(tokens, emb, pos, X);
    }

    for (int l = 0; l < LL; l++) {
        size_t base = (size_t)l * LYR_BLK;
        const __nv_bfloat16* qkvTh = WTh + base;
        const __nv_bfloat16* qkvTl = WTl + base;
        const __nv_bfloat16* w1Th  = WTh + base + (size_t)3 * DD * DD;
        const __nv_bfloat16* w1Tl  = WTl + base + (size_t)3 * DD * DD;
        const __nv_bfloat16* w2Th  = WTh + base + (size_t)3 * DD * DD + (size_t)DD * FF;
        const __nv_bfloat16* w2Tl  = WTl + base + (size_t)3 * DD * DD + (size_t)DD * FF;
        const float* b1_l = b1 + (size_t)l * FF;
        const float* b2_l = b2 + (size_t)l * DD;

        // h = ln1(x)
        ln_k<<<NROWS, 256>>>(X, H, g1 + (size_t)l * DD, bln1 + (size_t)l * DD);

        // q,k,v = h @ W   (one batched launch, z in {q,k,v})
        tcgemm(H, qkvTh, qkvTl, nullptr, QKV, NROWS, DD, DD, 1.f, nullptr, nullptr, 0, 3,
               0, (long)DD * DD, (long)NROWS * DD, 0);

        // VT (bf16 split, per batch)
        tsplit(Vp, VTh, VTl, TT, DD, BB, (long)TT * DD, (long)DD * TT);

        // s = (q @ k^T) * scale
        tcgemm(Q, nullptr, nullptr, Kp, S, TT, TT, DD, scale, nullptr, nullptr, 0, BB,
               (long)TT * DD, (long)TT * DD, (long)TT * TT, 0);

        // causal softmax
        {
            dim3 grid(TT, BB);
            softmax_k<<<grid, 256>>>(S);
        }

        // x = s @ v + x
        tcgemm(S, VTh, VTl, nullptr, X, TT, DD, TT, 1.f, nullptr, X, 0, BB,
               (long)TT * TT, (long)DD * TT, (long)TT * DD, (long)TT * DD);

        // y = ln2(x)
        ln_k<<<NROWS, 256>>>(X, H, g2 + (size_t)l * DD, bln2 + (size_t)l * DD);

        // ff = relu(y @ w1 + b1)
        tcgemm(H, w1Th, w1Tl, nullptr, Fh, NROWS, FF, DD, 1.f, b1_l, nullptr, 1, 1, 0, 0, 0, 0);

        // x = ff @ w2 + b2 + y
        tcgemm(Fh, w2Th, w2Tl, nullptr, X, NROWS, DD, FF, 1.f, b2_l, H, 0, 1, 0, 0, 0, 0);
    }

    // logits = x @ proj_w + proj_b
    tcgemm(X, WTh + PROJ_OFF, WTl + PROJ_OFF, nullptr, out, NROWS, VV, DD, 1.f, projb, nullptr, 0, 1,
           0, 0, 0, 0);
}

// round 7
// speedup vs baseline: 2.4770x; 1.1526x over previous
#include <cuda_runtime.h>
#include <cuda_bf16.h>
#include <math.h>
#include <stdint.h>

#define BB 2
#define TT 2048
#define DD 1024
#define LL 4
#define VV 32000
#define FF (4*DD)
#define NROWS (BB*TT)   // 4096

// WT scratch layout (elements): per layer: WqT,WkT,WvT (DD*DD each), w1T (DD*FF), w2T (FF*DD)
#define LYR_BLK (3*DD*DD + DD*FF + FF*DD)
#define PROJ_OFF ((size_t)LL*LYR_BLK)
#define WT_TOTAL (PROJ_OFF + (size_t)DD*VV)

// ---------------- scratch (device globals; no allocations allowed) ----------
__device__ float g_X[(size_t)NROWS*DD];
__device__ float g_Hf[(size_t)NROWS*DD];
__device__ float g_QKVf[(size_t)3*NROWS*DD];
__device__ float g_S[(size_t)BB*TT*TT];
__device__ __nv_bfloat16 g_Hh[(size_t)NROWS*DD],   g_Hl[(size_t)NROWS*DD];
__device__ __nv_bfloat16 g_Xh[(size_t)NROWS*DD],   g_Xl[(size_t)NROWS*DD];
__device__ __nv_bfloat16 g_QKVh[(size_t)3*NROWS*DD], g_QKVl[(size_t)3*NROWS*DD];
__device__ __nv_bfloat16 g_Sh[(size_t)BB*TT*TT],   g_Sl[(size_t)BB*TT*TT];
__device__ __nv_bfloat16 g_Fh[(size_t)NROWS*FF],   g_Fl[(size_t)NROWS*FF];
__device__ __nv_bfloat16 g_WTh[WT_TOTAL],          g_WTl[WT_TOTAL];
__device__ __nv_bfloat16 g_VTh[(size_t)BB*DD*TT],  g_VTl[(size_t)BB*DD*TT];

// ============================ helpers ========================================
__device__ __forceinline__ uint32_t smem_u32(const void* p) {
    uint32_t a;
    asm("{ .reg .u64 t; cvta.to.shared.u64 t, %1; cvt.u32.u64 %0, t; }" : "=r"(a) : "l"(p));
    return a;
}
// 64B-row swizzle: XOR byte bits [4:6) with bits [7:9)
#define SWZ64(o) ((o) ^ (((o) >> 3) & 0x30))

__device__ __forceinline__ void ldm_x4(uint32_t* r, uint32_t addr) {
    asm volatile("ldmatrix.sync.aligned.m8n8.x4.shared.b16 {%0,%1,%2,%3}, [%4];"
                 : "=r"(r[0]), "=r"(r[1]), "=r"(r[2]), "=r"(r[3]) : "r"(addr));
}
__device__ __forceinline__ void mma_bf16(float* d, const uint32_t* a, uint32_t b0, uint32_t b1) {
    asm volatile(
        "mma.sync.aligned.m16n8k16.row.col.f32.bf16.bf16.f32 "
        "{%0,%1,%2,%3}, {%4,%5,%6,%7}, {%8,%9}, {%0,%1,%2,%3};"
        : "+f"(d[0]), "+f"(d[1]), "+f"(d[2]), "+f"(d[3])
        : "r"(a[0]), "r"(a[1]), "r"(a[2]), "r"(a[3]), "r"(b0), "r"(b1));
}
__device__ __forceinline__ void cpa16(uint32_t dst, const void* src) {
    asm volatile("cp.async.cg.shared.global [%0], [%1], 16;" :: "r"(dst), "l"(src));
}
#define CP_COMMIT() asm volatile("cp.async.commit_group;" ::: "memory")
#define CP_WAIT2()  asm volatile("cp.async.wait_group 2;" ::: "memory")

__device__ __forceinline__ uint32_t pk2(__nv_bfloat16 a, __nv_bfloat16 b) {
    __nv_bfloat162 t = __halves2bfloat162(a, b);
    return *reinterpret_cast<uint32_t*>(&t);
}

// SMEM stage (32 KB): Ah @0, Al @8192, Bh @16384, Bl @24576. 128 rows x 32 bf16.
#define STG_SZ 32768
#define NSTG 4
#define SHM_TOTAL (NSTG*STG_SZ)
#define BK 32

// ---------------- all-bf16 split GEMM --------------------------------------
// C = alpha * (Ah+Al) @ (Bh+Bl)^T  (+bias)(+relu)(+addm), 3-term split MMA.
// A: [M][K] bf16 hi/lo. B: [N][K] bf16 hi/lo. Out: fp32 Cf and/or split Ch/Cl.
// cmode: 0 none, 1 = causal tile-skip (QK^T), 2 = causal K-limit (A=S case).
__global__ __launch_bounds__(256) void gemm_k(
    const __nv_bfloat16* __restrict__ Ahp, const __nv_bfloat16* __restrict__ Alp,
    const __nv_bfloat16* __restrict__ Bhp, const __nv_bfloat16* __restrict__ Blp,
    float* __restrict__ Cf,
    __nv_bfloat16* __restrict__ Ch, __nv_bfloat16* __restrict__ Cl,
    int M, int N, int K, float alpha,
    const float* __restrict__ bias,
    const float* __restrict__ addm,
    int relu, int cmode,
    long sA, long sB, long sC, long sAdd)
{
    extern __shared__ char smem[];
    const uint32_t smb = smem_u32(smem);
    const int tid = threadIdx.x;
    const long z = blockIdx.z;

    Ahp += z * sA; Alp += z * sA;
    Bhp += z * sB; Blp += z * sB;
    if (Cf) Cf += z * sC;
    if (Ch) { Ch += z * sC; Cl += z * sC; }
    if (addm) addm += z * sAdd;

    const int rowBlk = blockIdx.y * 128;
    const int colBlk = blockIdx.x * 128;
    if (cmode == 1 && colBlk >= rowBlk + 128) return;   // fully-masked QK tile

    int kMax = K;
    if (cmode == 2) { kMax = rowBlk + 128; if (kMax > K) kMax = K; }
    const int nCh = kMax / BK;

    const int lr = tid >> 1, half = tid & 1;
    const __nv_bfloat16* pa_h = Ahp + (long)(rowBlk + lr) * K + half * 16;
    const __nv_bfloat16* pa_l = Alp + (long)(rowBlk + lr) * K + half * 16;
    const __nv_bfloat16* pb_h = Bhp + (long)(colBlk + lr) * K + half * 16;
    const __nv_bfloat16* pb_l = Blp + (long)(colBlk + lr) * K + half * 16;
    const uint32_t o0 = SWZ64((uint32_t)(lr * 64 + half * 32));
    const uint32_t o1 = SWZ64((uint32_t)(lr * 64 + half * 32 + 16));

    // prologue: issue first NSTG-1 chunks
#pragma unroll
    for (int s = 0; s < NSTG - 1; s++) {
        if (s < nCh) {
            uint32_t sb = smb + (uint32_t)s * STG_SZ;
            long k0 = (long)s * BK;
            cpa16(sb + o0,         pa_h + k0);  cpa16(sb + o1,         pa_h + k0 + 8);
            cpa16(sb + 8192  + o0, pa_l + k0);  cpa16(sb + 8192  + o1, pa_l + k0 + 8);
            cpa16(sb + 16384 + o0, pb_h + k0);  cpa16(sb + 16384 + o1, pb_h + k0 + 8);
            cpa16(sb + 24576 + o0, pb_l + k0);  cpa16(sb + 24576 + o1, pb_l + k0 + 8);
        }
        CP_COMMIT();
    }

    float acc[4][4][4];
#pragma unroll
    for (int i = 0; i < 4; i++)
#pragma unroll
        for (int j = 0; j < 4; j++)
#pragma unroll
            for (int k = 0; k < 4; k++) acc[i][j][k] = 0.f;

    const int w = tid >> 5, lane = tid & 31;
    const int wm = (w & 1) * 64;
    const int wn = (w >> 1) * 32;

    for (int c = 0; c < nCh; c++) {
        CP_WAIT2();
        __syncthreads();
        const uint32_t sb = smb + (uint32_t)(c & (NSTG - 1)) * STG_SZ;
#pragma unroll
        for (int ks = 0; ks < 2; ks++) {
            uint32_t ah[4][4], al[4][4];
#pragma unroll
            for (int mt = 0; mt < 4; mt++) {
                uint32_t off = SWZ64((uint32_t)((wm + mt * 16 + (lane & 15)) * 64
                                                + ks * 32 + (lane >> 4) * 16));
                ldm_x4(ah[mt], sb + off);
                ldm_x4(al[mt], sb + 8192 + off);
            }
            uint32_t bh[4][2], bl[4][2];
#pragma unroll
            for (int nt2 = 0; nt2 < 2; nt2++) {
                uint32_t off = SWZ64((uint32_t)((wn + nt2 * 16 + ((lane >> 4) & 1) * 8 + (lane & 7)) * 64
                                                + ks * 32 + ((lane >> 3) & 1) * 16));
                uint32_t r[4];
                ldm_x4(r, sb + 16384 + off);
                bh[nt2 * 2][0] = r[0]; bh[nt2 * 2][1] = r[1];
                bh[nt2 * 2 + 1][0] = r[2]; bh[nt2 * 2 + 1][1] = r[3];
                ldm_x4(r, sb + 24576 + off);
                bl[nt2 * 2][0] = r[0]; bl[nt2 * 2][1] = r[1];
                bl[nt2 * 2 + 1][0] = r[2]; bl[nt2 * 2 + 1][1] = r[3];
            }
#pragma unroll
            for (int mt = 0; mt < 4; mt++)
#pragma unroll
                for (int nt = 0; nt < 4; nt++) {
                    mma_bf16(acc[mt][nt], ah[mt], bh[nt][0], bh[nt][1]);
                    mma_bf16(acc[mt][nt], ah[mt], bl[nt][0], bl[nt][1]);
                    mma_bf16(acc[mt][nt], al[mt], bh[nt][0], bh[nt][1]);
                }
        }
        // issue chunk c+NSTG-1 into stage (c-1)&3 (safe: all passed this iter's barrier)
        if (c + NSTG - 1 < nCh) {
            uint32_t sbn = smb + (uint32_t)((c + NSTG - 1) & (NSTG - 1)) * STG_SZ;
            long k0 = (long)(c + NSTG - 1) * BK;
            cpa16(sbn + o0,         pa_h + k0);  cpa16(sbn + o1,         pa_h + k0 + 8);
            cpa16(sbn + 8192  + o0, pa_l + k0);  cpa16(sbn + 8192  + o1, pa_l + k0 + 8);
            cpa16(sbn + 16384 + o0, pb_h + k0);  cpa16(sbn + 16384 + o1, pb_h + k0 + 8);
            cpa16(sbn + 24576 + o0, pb_l + k0);  cpa16(sbn + 24576 + o1, pb_l + k0 + 8);
        }
        CP_COMMIT();
    }

    // ---- epilogue ----
#pragma unroll
    for (int mt = 0; mt < 4; mt++) {
        int r0 = rowBlk + wm + mt * 16 + (lane >> 2);
#pragma unroll
        for (int nt = 0; nt < 4; nt++) {
            int cc = colBlk + wn + nt * 8 + (lane & 3) * 2;
            float2 v0, v1;
            v0.x = acc[mt][nt][0] * alpha; v0.y = acc[mt][nt][1] * alpha;
            v1.x = acc[mt][nt][2] * alpha; v1.y = acc[mt][nt][3] * alpha;
            if (bias) {
                float2 bb = *reinterpret_cast<const float2*>(bias + cc);
                v0.x += bb.x; v0.y += bb.y; v1.x += bb.x; v1.y += bb.y;
            }
            if (relu) {
                v0.x = fmaxf(v0.x, 0.f); v0.y = fmaxf(v0.y, 0.f);
                v1.x = fmaxf(v1.x, 0.f); v1.y = fmaxf(v1.y, 0.f);
            }
            if (addm) {
                float2 a0 = *reinterpret_cast<const float2*>(addm + (long)r0 * N + cc);
                float2 a1 = *reinterpret_cast<const float2*>(addm + (long)(r0 + 8) * N + cc);
                v0.x += a0.x; v0.y += a0.y; v1.x += a1.x; v1.y += a1.y;
            }
            if (Cf) {
                *reinterpret_cast<float2*>(Cf + (long)r0 * N + cc) = v0;
                *reinterpret_cast<float2*>(Cf + (long)(r0 + 8) * N + cc) = v1;
            }
            if (Ch) {
                __nv_bfloat16 h0 = __float2bfloat16(v0.x), h1 = __float2bfloat16(v0.y);
                __nv_bfloat16 h2 = __float2bfloat16(v1.x), h3 = __float2bfloat16(v1.y);
                *reinterpret_cast<uint32_t*>(Ch + (long)r0 * N + cc)       = pk2(h0, h1);
                *reinterpret_cast<uint32_t*>(Ch + (long)(r0 + 8) * N + cc) = pk2(h2, h3);
                *reinterpret_cast<uint32_t*>(Cl + (long)r0 * N + cc) =
                    pk2(__float2bfloat16(v0.x - __bfloat162float(h0)),
                        __float2bfloat16(v0.y - __bfloat162float(h1)));
                *reinterpret_cast<uint32_t*>(Cl + (long)(r0 + 8) * N + cc) =
                    pk2(__float2bfloat16(v1.x - __bfloat162float(h2)),
                        __float2bfloat16(v1.y - __bfloat162float(h3)));
            }
        }
    }
}

// ---------------- transpose + bf16 split: W[R][C] -> T[C][R] hi/lo ----------
__global__ void tsplit_k(const float* __restrict__ W,
                         __nv_bfloat16* __restrict__ Th, __nv_bfloat16* __restrict__ Tl,
                         int R, int C, long sIn, long sOut)
{
    __shared__ float t[32][33];
    W  += (long)blockIdx.z * sIn;
    Th += (long)blockIdx.z * sOut;
    Tl += (long)blockIdx.z * sOut;
    int c0 = blockIdx.x * 32, r0 = blockIdx.y * 32;
    int tx = threadIdx.x, ty = threadIdx.y;
#pragma unroll
    for (int j = 0; j < 32; j += 8)
        t[ty + j][tx] = W[(long)(r0 + ty + j) * C + c0 + tx];
    __syncthreads();
#pragma unroll
    for (int j = 0; j < 32; j += 8) {
        int oc = c0 + ty + j;
        float v = t[tx][ty + j];
        __nv_bfloat16 h = __float2bfloat16(v);
        float lo = v - __bfloat162float(h);
        Th[(long)oc * R + r0 + tx] = h;
        Tl[(long)oc * R + r0 + tx] = __float2bfloat16(lo);
    }
}

// ---------------- embed: x = emb[tok] + pos ---------------------------------
__global__ void embed_k(const int* __restrict__ tok,
                        const float* __restrict__ emb,
                        const float* __restrict__ pos,
                        float* __restrict__ X)
{
    int idx = blockIdx.x * blockDim.x + threadIdx.x;
    int total = NROWS * (DD / 4);
    if (idx >= total) return;
    int d4 = idx % (DD / 4);
    int bt = idx / (DD / 4);
    int t = bt % TT;
    int token = tok[bt];
    float4 e = reinterpret_cast<const float4*>(emb + (size_t)token * DD)[d4];
    float4 p = reinterpret_cast<const float4*>(pos + (size_t)t * DD)[d4];
    float4 o; o.x = e.x + p.x; o.y = e.y + p.y; o.z = e.z + p.z; o.w = e.w + p.w;
    reinterpret_cast<float4*>(X + (size_t)bt * DD)[d4] = o;
}

// ---------------- layernorm: fp32 in -> fp32 + bf16-split out ---------------
__global__ void ln_k(const float* __restrict__ X,
                     float* __restrict__ Yf,
                     __nv_bfloat16* __restrict__ Yh, __nv_bfloat16* __restrict__ Yl,
                     const float* __restrict__ g, const float* __restrict__ b)
{
    int row = blockIdx.x;
    int tid = threadIdx.x;
    const float4* x4 = reinterpret_cast<const float4*>(X + (size_t)row * DD);
    float4 v = x4[tid];
    __shared__ float sh[256];

    float s = v.x + v.y + v.z + v.w;
    sh[tid] = s; __syncthreads();
    for (int o = 128; o > 0; o >>= 1) { if (tid < o) sh[tid] += sh[tid + o]; __syncthreads(); }
    float mu = sh[0] * (1.0f / DD);
    __syncthreads();

    float c0 = v.x - mu, c1 = v.y - mu, c2 = v.z - mu, c3 = v.w - mu;
    sh[tid] = c0 * c0 + c1 * c1 + c2 * c2 + c3 * c3; __syncthreads();
    for (int o = 128; o > 0; o >>= 1) { if (tid < o) sh[tid] += sh[tid + o]; __syncthreads(); }
    float inv = rsqrtf(sh[0] * (1.0f / DD) + 1e-5f);

    float4 gv = reinterpret_cast<const float4*>(g)[tid];
    float4 bv = reinterpret_cast<const float4*>(b)[tid];
    float4 o4;
    o4.x = c0 * inv * gv.x + bv.x;
    o4.y = c1 * inv * gv.y + bv.y;
    o4.z = c2 * inv * gv.z + bv.z;
    o4.w = c3 * inv * gv.w + bv.w;
    reinterpret_cast<float4*>(Yf + (size_t)row * DD)[tid] = o4;

    __nv_bfloat16 h0 = __float2bfloat16(o4.x), h1 = __float2bfloat16(o4.y);
    __nv_bfloat16 h2 = __float2bfloat16(o4.z), h3 = __float2bfloat16(o4.w);
    uint2 hv, lv;
    hv.x = pk2(h0, h1); hv.y = pk2(h2, h3);
    lv.x = pk2(__float2bfloat16(o4.x - __bfloat162float(h0)),
               __float2bfloat16(o4.y - __bfloat162float(h1)));
    lv.y = pk2(__float2bfloat16(o4.z - __bfloat162float(h2)),
               __float2bfloat16(o4.w - __bfloat162float(h3)));
    *reinterpret_cast<uint2*>(Yh + (size_t)row * DD + tid * 4) = hv;
    *reinterpret_cast<uint2*>(Yl + (size_t)row * DD + tid * 4) = lv;
}

// ---------------- causal softmax: fp32 S -> bf16-split out ------------------
__global__ void softmax_k(const float* __restrict__ S,
                          __nv_bfloat16* __restrict__ Sh, __nv_bfloat16* __restrict__ Sl)
{
    int t = blockIdx.x, b = blockIdx.y;
    int tid = threadIdx.x;
    const float* row = S + ((size_t)b * TT + t) * TT;
    __nv_bfloat16* rh = Sh + ((size_t)b * TT + t) * TT;
    __nv_bfloat16* rl = Sl + ((size_t)b * TT + t) * TT;
    __shared__ float sh[256];

    float mx = -1e30f;
    for (int c = tid; c <= t; c += 256) mx = fmaxf(mx, row[c]);
    sh[tid] = mx; __syncthreads();
    for (int o = 128; o > 0; o >>= 1) { if (tid < o) sh[tid] = fmaxf(sh[tid], sh[tid + o]); __syncthreads(); }
    mx = sh[0]; __syncthreads();

    float sum = 0.f;
    for (int c = tid; c <= t; c += 256) sum += __expf(row[c] - mx);
    sh[tid] = sum; __syncthreads();
    for (int o = 128; o > 0; o >>= 1) { if (tid < o) sh[tid] += sh[tid + o]; __syncthreads(); }
    float inv = 1.0f / sh[0];

    for (int c = tid; c < TT; c += 256) {
        float p = (c <= t) ? __expf(row[c] - mx) * inv : 0.0f;
        __nv_bfloat16 h = __float2bfloat16(p);
        rh[c] = h;
        rl[c] = __float2bfloat16(p - __bfloat162float(h));
    }
}

// ---------------- host-side dispatch -----------------------------------------
static void gemm(const __nv_bfloat16* Ah, const __nv_bfloat16* Al,
                 const __nv_bfloat16* Bh, const __nv_bfloat16* Bl,
                 float* Cf, __nv_bfloat16* Ch, __nv_bfloat16* Cl,
                 int M, int N, int K, float alpha,
                 const float* bias, const float* addm, int relu, int cmode, int batch,
                 long sA, long sB, long sC, long sAdd)
{
    dim3 grid(N / 128, M / 128, batch), blk(256);
    gemm_k<<<grid, blk, SHM_TOTAL>>>(Ah, Al, Bh, Bl, Cf, Ch, Cl,
                                     M, N, K, alpha, bias, addm, relu, cmode,
                                     sA, sB, sC, sAdd);
}

static void tsplit(const float* W, __nv_bfloat16* Th, __nv_bfloat16* Tl,
                   int R, int C, int batch, long sIn, long sOut)
{
    dim3 g(C / 32, R / 32, batch), b(32, 8);
    tsplit_k<<<g, b>>>(W, Th, Tl, R, C, sIn, sOut);
}

extern "C" void kernel_launch(void* const* d_in, const int* in_sizes, int n_in,
                              void* d_out, int out_size)
{
    const int*   tokens = (const int*)  d_in[0];
    const float* emb    = (const float*)d_in[1];
    const float* pos    = (const float*)d_in[2];
    const float* Wq     = (const float*)d_in[3];
    const float* Wk     = (const float*)d_in[4];
    const float* Wv     = (const float*)d_in[5];
    const float* w1     = (const float*)d_in[6];
    const float* b1     = (const float*)d_in[7];
    const float* w2     = (const float*)d_in[8];
    const float* b2     = (const float*)d_in[9];
    const float* g1     = (const float*)d_in[10];
    const float* bln1   = (const float*)d_in[11];
    const float* g2     = (const float*)d_in[12];
    const float* bln2   = (const float*)d_in[13];
    const float* projw  = (const float*)d_in[14];
    const float* projb  = (const float*)d_in[15];
    float* out = (float*)d_out;

    cudaFuncSetAttribute(gemm_k, cudaFuncAttributeMaxDynamicSharedMemorySize, SHM_TOTAL);

    float *X, *Hf, *QKVf, *S;
    __nv_bfloat16 *Hh, *Hl, *Xh, *Xl, *QKVh, *QKVl, *Sh, *Sl, *Fh, *Fl, *WTh, *WTl, *VTh, *VTl;
    cudaGetSymbolAddress((void**)&X,    g_X);
    cudaGetSymbolAddress((void**)&Hf,   g_Hf);
    cudaGetSymbolAddress((void**)&QKVf, g_QKVf);
    cudaGetSymbolAddress((void**)&S,    g_S);
    cudaGetSymbolAddress((void**)&Hh,   g_Hh);   cudaGetSymbolAddress((void**)&Hl,   g_Hl);
    cudaGetSymbolAddress((void**)&Xh,   g_Xh);   cudaGetSymbolAddress((void**)&Xl,   g_Xl);
    cudaGetSymbolAddress((void**)&QKVh, g_QKVh); cudaGetSymbolAddress((void**)&QKVl, g_QKVl);
    cudaGetSymbolAddress((void**)&Sh,   g_Sh);   cudaGetSymbolAddress((void**)&Sl,   g_Sl);
    cudaGetSymbolAddress((void**)&Fh,   g_Fh);   cudaGetSymbolAddress((void**)&Fl,   g_Fl);
    cudaGetSymbolAddress((void**)&WTh,  g_WTh);  cudaGetSymbolAddress((void**)&WTl,  g_WTl);
    cudaGetSymbolAddress((void**)&VTh,  g_VTh);  cudaGetSymbolAddress((void**)&VTl,  g_VTl);

    const float scale = 0.03125f;   // 1/sqrt(1024)
    const long ND = (long)NROWS * DD;

    // ---- weight prepass: transpose + bf16 hi/lo split -----------------------
    for (int l = 0; l < LL; l++) {
        size_t base = (size_t)l * LYR_BLK;
        tsplit(Wq + (size_t)l * DD * DD, WTh + base,                   WTl + base,                   DD, DD, 1, 0, 0);
        tsplit(Wk + (size_t)l * DD * DD, WTh + base + (size_t)DD*DD,   WTl + base + (size_t)DD*DD,   DD, DD, 1, 0, 0);
        tsplit(Wv + (size_t)l * DD * DD, WTh + base + (size_t)2*DD*DD, WTl + base + (size_t)2*DD*DD, DD, DD, 1, 0, 0);
        tsplit(w1 + (size_t)l * DD * FF, WTh + base + (size_t)3*DD*DD, WTl + base + (size_t)3*DD*DD, DD, FF, 1, 0, 0);
        tsplit(w2 + (size_t)l * FF * DD, WTh + base + (size_t)3*DD*DD + (size_t)DD*FF,
                                         WTl + base + (size_t)3*DD*DD + (size_t)DD*FF, FF, DD, 1, 0, 0);
    }
    tsplit(projw, WTh + PROJ_OFF, WTl + PROJ_OFF, DD, VV, 1, 0, 0);

    // ---- embed --------------------------------------------------------------
    {
        int total = NROWS * (DD / 4);
        embed_k<<<(total + 255) / 256, 256>>>(tokens, emb, pos, X);
    }

    for (int l = 0; l < LL; l++) {
        size_t base = (size_t)l * LYR_BLK;
        const __nv_bfloat16* qkvTh = WTh + base;
        const __nv_bfloat16* qkvTl = WTl + base;
        const __nv_bfloat16* w1Th  = WTh + base + (size_t)3 * DD * DD;
        const __nv_bfloat16* w1Tl  = WTl + base + (size_t)3 * DD * DD;
        const __nv_bfloat16* w2Th  = WTh + base + (size_t)3 * DD * DD + (size_t)DD * FF;
        const __nv_bfloat16* w2Tl  = WTl + base + (size_t)3 * DD * DD + (size_t)DD * FF;
        const float* b1_l = b1 + (size_t)l * FF;
        const float* b2_l = b2 + (size_t)l * DD;

        // h = ln1(x)  (fp32 + split)
        ln_k<<<NROWS, 256>>>(X, Hf, Hh, Hl, g1 + (size_t)l * DD, bln1 + (size_t)l * DD);

        // q,k,v = h @ W   (z batched over q/k/v; out fp32 + split)
        gemm(Hh, Hl, qkvTh, qkvTl, QKVf, QKVh, QKVl, NROWS, DD, DD, 1.f,
             nullptr, nullptr, 0, 0, 3, 0, (long)DD * DD, ND, 0);

        // VT split (from V fp32, z=2 slice)
        tsplit(QKVf + 2 * ND, VTh, VTl, TT, DD, BB, (long)TT * DD, (long)DD * TT);

        // s = (q @ k^T) * scale   (causal tile-skip; out fp32)
        gemm(QKVh, QKVl, QKVh + ND, QKVl + ND, S, nullptr, nullptr,
             TT, TT, DD, scale, nullptr, nullptr, 0, 1, BB,
             (long)TT * DD, (long)TT * DD, (long)TT * TT, 0);

        // causal softmax -> split S
        {
            dim3 grid(TT, BB);
            softmax_k<<<grid, 256>>>(S, Sh, Sl);
        }

        // x = s @ v + x   (K-limit via causal zeros; out fp32)
        gemm(Sh, Sl, VTh, VTl, X, nullptr, nullptr, TT, DD, TT, 1.f,
             nullptr, X, 0, 2, BB,
             (long)TT * TT, (long)DD * TT, (long)TT * DD, (long)TT * DD);

        // y = ln2(x)  (fp32 + split)
        ln_k<<<NROWS, 256>>>(X, Hf, Hh, Hl, g2 + (size_t)l * DD, bln2 + (size_t)l * DD);

        // ff = relu(y @ w1 + b1)  (split out only)
        gemm(Hh, Hl, w1Th, w1Tl, nullptr, Fh, Fl, NROWS, FF, DD, 1.f,
             b1_l, nullptr, 1, 0, 1, 0, 0, 0, 0);

        // x = ff @ w2 + b2 + y  (fp32 + split out)
        gemm(Fh, Fl, w2Th, w2Tl, X, Xh, Xl, NROWS, DD, FF, 1.f,
             b2_l, Hf, 0, 0, 1, 0, 0, 0, 0);
    }

    // logits = x @ proj_w + proj_b
    gemm(Xh, Xl, WTh + PROJ_OFF, WTl + PROJ_OFF, out, nullptr, nullptr,
         NROWS, VV, DD, 1.f, projb, nullptr, 0, 0, 1, 0, 0, 0, 0);
}